// round 17
// baseline (speedup 1.0000x reference)
#include <cuda_runtime.h>
#include <math.h>
#include <stddef.h>

#define Nh   1024
#define LSEQ 16384
#define NT1  512
#define NT2  32
#define KS   4
#define KCH  256          // Nh / KS

// ---------------- static device scratch ----------------
__device__ float g_S[Nh*Nh];
__device__ float g_T[Nh*Nh];
__device__ float g_P[Nh*Nh];
__device__ float g_M[Nh*Nh];
__device__ float g_U[NT1*Nh];
__device__ float g_W[NT2*Nh];
__device__ float g_K[LSEQ];
__device__ float g_Q [KS*Nh*Nh];     // split-K partials (full GEMMs)   16 MB
__device__ float g_QU[KS*256*Nh];    // split-K partials (U-extension)   4 MB

// ---------------- helpers ----------------
__device__ __forceinline__ unsigned smem_u32(const void* p) {
    return (unsigned)__cvta_generic_to_shared(p);
}
__device__ __forceinline__ void cp16(unsigned dst, const void* src) {
    asm volatile("cp.async.cg.shared.global [%0], [%1], 16;\n" :: "r"(dst), "l"(src));
}
__device__ __forceinline__ void ffma2(unsigned long long& acc,
                                      unsigned long long a, unsigned long long b) {
    asm("fma.rn.f32x2 %0, %1, %2, %0;" : "+l"(acc) : "l"(a), "l"(b));
}
__device__ __forceinline__ unsigned long long dupf(float x) {
    unsigned long long r; unsigned u = __float_as_uint(x);
    asm("mov.b64 %0,{%1,%1};" : "=l"(r) : "r"(u));
    return r;
}

// ---------------- elementwise ----------------
__global__ void k_prep(const float* __restrict__ A, const float* __restrict__ logd,
                       float* __restrict__ S) {
    int i = blockIdx.x*blockDim.x + threadIdx.x;
    float d = (float)exp((double)logd[0]);
    S[i] = 0.5f*d*A[i];
}
__global__ void k_copy(const float* __restrict__ src, float* __restrict__ dst, int n) {
    int i = blockIdx.x*blockDim.x + threadIdx.x;
    if (i < n) dst[i] = src[i];
}

// ---------------- partial GEMM: 128x64 tile, BK=16, 256 thr, 4Mx8N micro ----
// A-dup variant: acc pairs along N; B pairs come free from conflict-free LDS.128;
// only 4 A-scalars duplicated per k (vs 8 B-dups before).
#define BM 128
#define BN 64
#define BK 16
#define NTHR 256

__device__ __forceinline__ void gemm_partial(const float* __restrict__ A,
                                             const float* __restrict__ B,
                                             float* __restrict__ Cp,
                                             int Mrows, int bm, int bn, int k0) {
    __shared__ __align__(16) float As[2][BK][BM];   // 16 KB, transposed As[b][k][m]
    __shared__ __align__(16) float Bs[2][BK][BN];   // 8 KB
    const int tid = threadIdx.x;
    const int tx = tid & 7;          // n groups: {tx*4..+3} u {32+tx*4..+3}
    const int ty = tid >> 3;         // m0 = ty*4  (ty in 0..31)

    // acc[m][j]: m in 0..3 rows; j: 0->(tx*4,+1) 1->(tx*4+2,+3) 2->(32+tx*4,+1) 3->(32+tx*4+2,+3)
    unsigned long long acc[4][4];
    #pragma unroll
    for (int m = 0; m < 4; m++)
        #pragma unroll
        for (int j = 0; j < 4; j++) acc[m][j] = 0ULL;

    // A staging: 128 rows x 16 k = 512 float4; 2 per thread
    const int ar  = tid >> 1;              // 0..127
    const int af0 = (tid & 1) << 3;        // k-offset 0 or 8
    const bool arow_ok = (bm + ar) < Mrows;
    const float* arow = A + (size_t)(bm + ar)*Nh + af0;
    // B: 16 k-rows x 64 cols = 256 float4; 1 cp.async per thread
    const int brow = tid >> 4;             // 0..15
    const int bq4  = (tid & 15) << 2;      // col quad
    const unsigned bs_addr[2] = { smem_u32(&Bs[0][0][0]), smem_u32(&Bs[1][0][0]) };

    float4 va0, va1;
    // ---- prologue: tile 0 ----
    va0 = arow_ok ? *(const float4*)(arow + k0)     : make_float4(0.f,0.f,0.f,0.f);
    va1 = arow_ok ? *(const float4*)(arow + k0 + 4) : make_float4(0.f,0.f,0.f,0.f);
    cp16(bs_addr[0] + (unsigned)(brow*BN + bq4)*4, B + (size_t)(k0 + brow)*Nh + bn + bq4);
    asm volatile("cp.async.commit_group;\n" ::: "memory");
    As[0][af0+0][ar] = va0.x; As[0][af0+1][ar] = va0.y;
    As[0][af0+2][ar] = va0.z; As[0][af0+3][ar] = va0.w;
    As[0][af0+4][ar] = va1.x; As[0][af0+5][ar] = va1.y;
    As[0][af0+6][ar] = va1.z; As[0][af0+7][ar] = va1.w;
    asm volatile("cp.async.wait_group 0;\n" ::: "memory");
    __syncthreads();

    const int ntiles = KCH / BK;   // 16
    int buf = 0;
    for (int t = 0; t < ntiles; t++) {
        if (t + 1 < ntiles) {
            int kt = k0 + (t + 1)*BK;
            va0 = arow_ok ? *(const float4*)(arow + kt)     : make_float4(0.f,0.f,0.f,0.f);
            va1 = arow_ok ? *(const float4*)(arow + kt + 4) : make_float4(0.f,0.f,0.f,0.f);
            unsigned bsn = bs_addr[buf ^ 1];
            cp16(bsn + (unsigned)(brow*BN + bq4)*4, B + (size_t)(kt + brow)*Nh + bn + bq4);
            asm volatile("cp.async.commit_group;\n" ::: "memory");
        }
        #pragma unroll
        for (int k = 0; k < BK; k++) {
            float4 af = *(const float4*)(&As[buf][k][ty*4]);
            ulonglong2 bA = *(const ulonglong2*)(&Bs[buf][k][tx*4]);        // lane-contig
            ulonglong2 bB = *(const ulonglong2*)(&Bs[buf][k][32 + tx*4]);   // lane-contig
            unsigned long long ad[4] = {dupf(af.x), dupf(af.y), dupf(af.z), dupf(af.w)};
            unsigned long long bb[4] = {bA.x, bA.y, bB.x, bB.y};
            #pragma unroll
            for (int m = 0; m < 4; m++)
                #pragma unroll
                for (int j = 0; j < 4; j++)
                    ffma2(acc[m][j], ad[m], bb[j]);
        }
        if (t + 1 < ntiles) {
            int nb = buf ^ 1;
            As[nb][af0+0][ar] = va0.x; As[nb][af0+1][ar] = va0.y;
            As[nb][af0+2][ar] = va0.z; As[nb][af0+3][ar] = va0.w;
            As[nb][af0+4][ar] = va1.x; As[nb][af0+5][ar] = va1.y;
            As[nb][af0+6][ar] = va1.z; As[nb][af0+7][ar] = va1.w;
            asm volatile("cp.async.wait_group 0;\n" ::: "memory");
        }
        __syncthreads();
        buf ^= 1;
    }

    // ---- write partial tile (pairs along N) ----
    #pragma unroll
    for (int m = 0; m < 4; m++) {
        int row = bm + ty*4 + m;
        if (row >= Mrows) continue;
        #pragma unroll
        for (int j = 0; j < 4; j++) {
            int nc = bn + ((j >> 1) ? 32 : 0) + tx*4 + (j & 1)*2;
            float2 v;
            v.x = __uint_as_float((unsigned)(acc[m][j]));
            v.y = __uint_as_float((unsigned)(acc[m][j] >> 32));
            *(float2*)(Cp + (size_t)row*Nh + nc) = v;
        }
    }
}

__global__ __launch_bounds__(NTHR, 2)
void k_gemm_part(const float* __restrict__ A, const float* __restrict__ B,
                 float* __restrict__ Q, int Mrows) {
    gemm_partial(A, B, Q + (size_t)blockIdx.z*Nh*Nh, Mrows,
                 blockIdx.y*BM, blockIdx.x*BN, blockIdx.z*KCH);
}

// Fused doubling partials: y<8 -> squaring into Qs ; y>=8 -> U-ext into QU
__global__ __launch_bounds__(NTHR, 2)
void k_step_part(const float* __restrict__ U, const float* __restrict__ Pw,
                 int rows, float* __restrict__ Qs, float* __restrict__ QU) {
    int by = blockIdx.y, z = blockIdx.z;
    if (by < 8)
        gemm_partial(Pw, Pw, Qs + (size_t)z*Nh*Nh, Nh, by*BM, blockIdx.x*BN, z*KCH);
    else
        gemm_partial(U, Pw, QU + (size_t)z*(256*Nh), rows, (by - 8)*BM, blockIdx.x*BN, z*KCH);
}

// ---------------- combine kernels ----------------
#define MODE_P0 1   // C = I + E + sum
#define MODE_R  2   // C = 2I - E + sum
#define MODE_PM 3   // C = sum ; C2 = 2*sum - I

__device__ __forceinline__ float4 sum4(const float4* Q, size_t q, size_t SZ) {
    float4 a = Q[q], b = Q[q+SZ], c = Q[q+2*SZ], d = Q[q+3*SZ];
    float4 v;
    v.x = (a.x + b.x) + (c.x + d.x);
    v.y = (a.y + b.y) + (c.y + d.y);
    v.z = (a.z + b.z) + (c.z + d.z);
    v.w = (a.w + b.w) + (c.w + d.w);
    return v;
}

template<int MODE>
__global__ void k_comb(const float* __restrict__ Q, const float* __restrict__ E,
                       float* __restrict__ C, float* __restrict__ C2) {
    int q = blockIdx.x*blockDim.x + threadIdx.x;     // quad id (262144 total)
    const size_t SZ = (size_t)Nh*Nh/4;
    float4 v = sum4((const float4*)Q, (size_t)q, SZ);
    int m  = q >> 8;
    int nc = (q & 255) << 2;
    if (MODE == MODE_P0) {
        float4 e = ((const float4*)E)[q];
        v.x += e.x; v.y += e.y; v.z += e.z; v.w += e.w;
        if (m == nc)   v.x += 1.f; if (m == nc+1) v.y += 1.f;
        if (m == nc+2) v.z += 1.f; if (m == nc+3) v.w += 1.f;
    }
    if (MODE == MODE_R) {
        float4 e = ((const float4*)E)[q];
        v.x -= e.x; v.y -= e.y; v.z -= e.z; v.w -= e.w;
        if (m == nc)   v.x += 2.f; if (m == nc+1) v.y += 2.f;
        if (m == nc+2) v.z += 2.f; if (m == nc+3) v.w += 2.f;
    }
    ((float4*)C)[q] = v;
    if (MODE == MODE_PM) {
        float4 w;
        w.x = 2.f*v.x; w.y = 2.f*v.y; w.z = 2.f*v.z; w.w = 2.f*v.w;
        if (m == nc)   w.x -= 1.f; if (m == nc+1) w.y -= 1.f;
        if (m == nc+2) w.z -= 1.f; if (m == nc+3) w.w -= 1.f;
        ((float4*)C2)[q] = w;
    }
}

__global__ void k_stepcomb(const float* __restrict__ Qs, const float* __restrict__ QU,
                           float* __restrict__ Psq, float* __restrict__ Unext, int rows) {
    int q = blockIdx.x*blockDim.x + threadIdx.x;
    const size_t SZ = (size_t)Nh*Nh/4;
    if (q < (int)SZ) {
        ((float4*)Psq)[q] = sum4((const float4*)Qs, (size_t)q, SZ);
    } else {
        int qq = q - (int)SZ;
        if ((qq >> 8) < rows) {
            const size_t SU = (size_t)256*Nh/4;
            ((float4*)Unext)[qq] = sum4((const float4*)QU, (size_t)qq, SU);
        }
    }
}

// ---------------- matvec: y = Mat @ x, optional scale exp(logd) ----------------
__global__ void k_matvec(const float* __restrict__ Mat, const float* __restrict__ x,
                         float* __restrict__ y, const float* __restrict__ logd) {
    int gw   = (blockIdx.x*blockDim.x + threadIdx.x) >> 5;
    int lane = threadIdx.x & 31;
    if (gw >= Nh) return;
    const float4* r  = (const float4*)(Mat + (size_t)gw*Nh);
    const float4* xv = (const float4*)x;
    float acc = 0.f;
    #pragma unroll 4
    for (int j = lane; j < Nh/4; j += 32) {
        float4 a = r[j], b = xv[j];
        acc += a.x*b.x + a.y*b.y + a.z*b.z + a.w*b.w;
    }
    #pragma unroll
    for (int o = 16; o; o >>= 1) acc += __shfl_down_sync(0xffffffffu, acc, o);
    if (lane == 0) {
        float s = 1.f;
        if (logd) s = (float)exp((double)logd[0]);
        y[gw] = s*acc;
    }
}

// ---------------- K[t1 + 512*t2] = dot(U[t1,:], W[t2,:]) ----------------
__global__ void k_gk(const float* __restrict__ U, const float* __restrict__ W,
                     float* __restrict__ K) {
    int gw   = (blockIdx.x*blockDim.x + threadIdx.x) >> 5;
    int lane = threadIdx.x & 31;
    if (gw >= LSEQ) return;
    int t1 = gw & (NT1 - 1);
    int t2 = gw >> 9;
    const float4* u = (const float4*)(U + (size_t)t1*Nh);
    const float4* w = (const float4*)(W + (size_t)t2*Nh);
    float acc = 0.f;
    #pragma unroll 4
    for (int j = lane; j < Nh/4; j += 32) {
        float4 a = u[j], b = w[j];
        acc += a.x*b.x + a.y*b.y + a.z*b.z + a.w*b.w;
    }
    #pragma unroll
    for (int o = 16; o; o >>= 1) acc += __shfl_down_sync(0xffffffffu, acc, o);
    if (lane == 0) K[gw] = acc;
}

// ---------------- causal conv: Y[k] = sum_{t<=k} K[t] X[k-t] + D*X[k] ----------------
__global__ __launch_bounds__(128)
void k_conv(const float* __restrict__ X, const float* __restrict__ K,
            const float* __restrict__ D, float* __restrict__ Y) {
    __shared__ float Ks[256];
    __shared__ float Xs[128];
    const int i  = blockIdx.x;
    const int kk = threadIdx.x;
    float acc = 0.f;
    for (int j = 0; j <= i; j++) {
        int base = (i - j) << 7;
        __syncthreads();
        Xs[kk] = X[(j << 7) + kk];
        int i0 = base - 128 + kk;
        Ks[kk]       = (i0 >= 0) ? K[i0] : 0.f;
        Ks[kk + 128] = K[base + kk];
        __syncthreads();
        #pragma unroll 8
        for (int t = 0; t < 128; t++)
            acc += Ks[kk + 128 - t] * Xs[t];
    }
    int k = (i << 7) + kk;
    Y[k] = acc + D[0]*X[k];
}

// ---------------- host ----------------
extern "C" void kernel_launch(void* const* d_in, const int* in_sizes, int n_in,
                              void* d_out, int out_size) {
    int iX=-1, iA=-1, iB=-1, iC=-1, iD=-1, iLd=-1;
    for (int i = 0; i < n_in; i++) {
        int s = in_sizes[i];
        if      (s == Nh*Nh) iA = i;
        else if (s == LSEQ)  iX = i;
        else if (s == Nh)    { if (iB < 0) iB = i; else iC = i; }
        else if (s == 1)     { if (iD < 0) iD = i; else iLd = i; }
    }
    const float* X    = (const float*)d_in[iX];
    const float* A    = (const float*)d_in[iA];
    const float* Bv   = (const float*)d_in[iB];
    const float* Cv   = (const float*)d_in[iC];
    const float* Dv   = (const float*)d_in[iD];
    const float* logd = (const float*)d_in[iLd];
    float* Y = (float*)d_out;
    (void)out_size;

    float *pS, *pT, *pP, *pM, *pU, *pW, *pK, *pQ, *pQU;
    cudaGetSymbolAddress((void**)&pS, g_S);
    cudaGetSymbolAddress((void**)&pT, g_T);
    cudaGetSymbolAddress((void**)&pP, g_P);
    cudaGetSymbolAddress((void**)&pM, g_M);
    cudaGetSymbolAddress((void**)&pU, g_U);
    cudaGetSymbolAddress((void**)&pW, g_W);
    cudaGetSymbolAddress((void**)&pK, g_K);
    cudaGetSymbolAddress((void**)&pQ, g_Q);
    cudaGetSymbolAddress((void**)&pQU, g_QU);

    const int EW = (Nh*Nh)/256;
    dim3 gp(Nh/BN, Nh/BM, KS);     // 16 x 8 x 4 = 512 CTAs
    const int CB = (Nh*Nh/4)/256;  // 1024 combine blocks

    // S = (d/2) A   -> g_S
    k_prep<<<EW, 256>>>(A, logd, pS);
    // P0 = I + S + S^2                      -> g_P
    k_gemm_part<<<gp, NTHR>>>(pS, pS, pQ, Nh);
    k_comb<MODE_P0><<<CB, 256>>>(pQ, pS, pP, nullptr);
    // R  = 2I - P0 + S@P0                   -> g_T
    k_gemm_part<<<gp, NTHR>>>(pS, pP, pQ, Nh);
    k_comb<MODE_R ><<<CB, 256>>>(pQ, pP, pT, nullptr);
    // P  = P0@R -> g_S ;  M = 2P - I -> g_M
    k_gemm_part<<<gp, NTHR>>>(pP, pT, pQ, Nh);
    k_comb<MODE_PM><<<CB, 256>>>(pQ, nullptr, pS, pM);

    k_matvec<<<128, 256>>>(pS, Bv, pW, logd);      // W[0] = dB = d * P @ B
    k_copy<<<4, 256>>>(Cv, pU, Nh);                // U[0] = c

    // Fused doubling: U[rows..2rows) = U @ M^{2^s}, M^{2^{s+1}} = (M^{2^s})^2
    float* pw   = pM;
    float* ping = pP;
    float* pong = pT;
    int rows = 1;
    for (int s = 0; s < 9; s++) {
        int urt = (rows + BM - 1)/BM;          // 1 (rows<=128) or 2 (rows=256)
        dim3 gs(Nh/BN, 8 + urt, KS);
        k_step_part<<<gs, NTHR>>>(pU, pw, rows, pQ, pQU);
        int totq = Nh*Nh/4 + rows*(Nh/4);
        k_stepcomb<<<(totq + 255)/256, 256>>>(pQ, pQU, ping, pU + (size_t)rows*Nh, rows);
        pw = ping;
        float* tmp = ping; ping = pong; pong = tmp;
        rows <<= 1;
    }
    // pw = M^512

    // W[t] = M^512 @ W[t-1], t = 1..31
    for (int t = 1; t < NT2; t++)
        k_matvec<<<128, 256>>>(pw, pW + (size_t)(t-1)*Nh, pW + (size_t)t*Nh, nullptr);

    // K[t1 + 512*t2] = U[t1] . W[t2]
    k_gk<<<LSEQ/8, 256>>>(pU, pW, pK);

    // y = K (*) X + D*X
    k_conv<<<LSEQ/128, 128>>>(X, pK, Dv, Y);
}